// round 4
// baseline (speedup 1.0000x reference)
#include <cuda_runtime.h>
#include <cstdint>

typedef unsigned long long ull;

#define TOKENS 4096
#define PDIM   1024
#define PHALF  512
#define NKEYS  512
#define PTOPK  32

// ---------------- scratch (static device allocations; no cudaMalloc) ----------------
__device__ float g_query[TOKENS * PDIM];
__device__ float g_gate [TOKENS * PDIM];
__device__ float g_s1   [TOKENS * NKEYS];
__device__ float g_s2   [TOKENS * NKEYS];
__device__ float g_mid  [TOKENS * PDIM];
__device__ int   g_tidx [TOKENS * PTOPK];
__device__ float g_tw   [TOKENS * PTOPK];

// ---------------- f32x2 packed-FMA helpers (Blackwell FFMA2 path) ----------------
__device__ __forceinline__ void fma2(ull &acc, ull a, ull b) {
    asm("fma.rn.f32x2 %0, %1, %2, %3;" : "=l"(acc) : "l"(a), "l"(b), "l"(acc));
}
__device__ __forceinline__ ull dup2(float a) {
    ull r; asm("mov.b64 %0, {%1, %1};" : "=l"(r) : "f"(a)); return r;
}
__device__ __forceinline__ float2 upk2(ull v) {
    float2 r; asm("mov.b64 {%0, %1}, %2;" : "=f"(r.x), "=f"(r.y) : "l"(v)); return r;
}

// ---------------- generic TN SGEMM: C[M,N] = A[M,K] * B[N,K]^T (+bias, optional silu) ----
#define BM 128
#define BN 128
#define BK 16

__global__ __launch_bounds__(256, 2)
void gemm_tn(const float* __restrict__ A, const float* __restrict__ B,
             const float* __restrict__ bias, float* __restrict__ C,
             int K, int lda, int ldb, int ldc, int act)
{
    __shared__ __align__(16) float As[BK][BM + 4];
    __shared__ __align__(16) float Bs[BK][BN + 4];

    const int tid = threadIdx.x;
    const int bm  = blockIdx.y * BM;
    const int bn  = blockIdx.x * BN;
    const int lr  = tid >> 2;          // 0..63 (load row)
    const int lc  = (tid & 3) * 4;     // 0,4,8,12 (load col, k-direction)
    const int tx  = tid & 15;
    const int ty  = tid >> 4;

    const float* Ap0 = A + (size_t)(bm + lr) * lda + lc;
    const float* Ap1 = Ap0 + (size_t)64 * lda;
    const float* Bp0 = B + (size_t)(bn + lr) * ldb + lc;
    const float* Bp1 = Bp0 + (size_t)64 * ldb;

    float4 av0 = *(const float4*)Ap0;
    float4 av1 = *(const float4*)Ap1;
    float4 bv0 = *(const float4*)Bp0;
    float4 bv1 = *(const float4*)Bp1;

    ull acc[8][4];
    #pragma unroll
    for (int r = 0; r < 8; r++)
        #pragma unroll
        for (int c = 0; c < 4; c++) acc[r][c] = 0ull;

    for (int k0 = 0; k0 < K; k0 += BK) {
        __syncthreads();
        // transpose-store into smem: As[k][m], Bs[k][n]
        As[lc + 0][lr]      = av0.x; As[lc + 1][lr]      = av0.y;
        As[lc + 2][lr]      = av0.z; As[lc + 3][lr]      = av0.w;
        As[lc + 0][lr + 64] = av1.x; As[lc + 1][lr + 64] = av1.y;
        As[lc + 2][lr + 64] = av1.z; As[lc + 3][lr + 64] = av1.w;
        Bs[lc + 0][lr]      = bv0.x; Bs[lc + 1][lr]      = bv0.y;
        Bs[lc + 2][lr]      = bv0.z; Bs[lc + 3][lr]      = bv0.w;
        Bs[lc + 0][lr + 64] = bv1.x; Bs[lc + 1][lr + 64] = bv1.y;
        Bs[lc + 2][lr + 64] = bv1.z; Bs[lc + 3][lr + 64] = bv1.w;
        __syncthreads();

        if (k0 + BK < K) {  // prefetch next tile while computing this one
            av0 = *(const float4*)(Ap0 + k0 + BK);
            av1 = *(const float4*)(Ap1 + k0 + BK);
            bv0 = *(const float4*)(Bp0 + k0 + BK);
            bv1 = *(const float4*)(Bp1 + k0 + BK);
        }

        #pragma unroll
        for (int k = 0; k < BK; k++) {
            float4 a0 = *(const float4*)&As[k][ty * 8];
            float4 a1 = *(const float4*)&As[k][ty * 8 + 4];
            ulonglong2 bq0 = *(const ulonglong2*)&Bs[k][tx * 8];
            ulonglong2 bq1 = *(const ulonglong2*)&Bs[k][tx * 8 + 4];
            ull bb[4] = { bq0.x, bq0.y, bq1.x, bq1.y };
            ull aa[8] = { dup2(a0.x), dup2(a0.y), dup2(a0.z), dup2(a0.w),
                          dup2(a1.x), dup2(a1.y), dup2(a1.z), dup2(a1.w) };
            #pragma unroll
            for (int r = 0; r < 8; r++)
                #pragma unroll
                for (int c = 0; c < 4; c++) fma2(acc[r][c], aa[r], bb[c]);
        }
    }

    #pragma unroll
    for (int c = 0; c < 4; c++) {
        int col = bn + tx * 8 + 2 * c;
        float b0 = 0.f, b1 = 0.f;
        if (bias) { b0 = bias[col]; b1 = bias[col + 1]; }
        #pragma unroll
        for (int r = 0; r < 8; r++) {
            float2 v = upk2(acc[r][c]);
            v.x += b0; v.y += b1;
            if (act) {  // silu
                v.x = v.x * (1.f / (1.f + __expf(-v.x)));
                v.y = v.y * (1.f / (1.f + __expf(-v.y)));
            }
            *(float2*)&C[(size_t)(bm + ty * 8 + r) * ldc + col] = v;
        }
    }
}

// ---------------- top-k (warp per token, registers only) ----------------
// Keys pack (orderable-float << 32) | (0xFFFFFFFF - idx): max-key == jax top_k
// semantics (value descending, ties -> smaller index).
__device__ __forceinline__ unsigned ford(float v) {
    unsigned u = __float_as_uint(v);
    return (u & 0x80000000u) ? ~u : (u | 0x80000000u);
}
__device__ __forceinline__ float funord(unsigned k) {
    unsigned u = (k & 0x80000000u) ? (k ^ 0x80000000u) : ~k;
    return __uint_as_float(u);
}
__device__ __forceinline__ ull mkkey(float v, int idx) {
    return ((ull)ford(v) << 32) | (unsigned)(0xFFFFFFFFu - (unsigned)idx);
}

// PMAJ=false: idx = j*32 + lane (owner = idx&31, slot = idx>>5)
// PMAJ=true : idx = lane*32 + j (owner = idx>>5, slot = idx&31)
template <int NL, bool PMAJ>
__device__ __forceinline__ void select32(ull* kk, int lane, float &ov, int &oi) {
    for (int it = 0; it < PTOPK; ++it) {
        ull best = kk[0];
        #pragma unroll
        for (int j = 1; j < NL; j++) if (kk[j] > best) best = kk[j];
        #pragma unroll
        for (int o = 16; o > 0; o >>= 1) {
            ull t = __shfl_xor_sync(0xFFFFFFFFu, best, o);
            if (t > best) best = t;
        }
        int idx = (int)(0xFFFFFFFFu - (unsigned)best);
        if (lane == it) { ov = funord((unsigned)(best >> 32)); oi = idx; }
        int owner = PMAJ ? (idx >> 5) : (idx & 31);
        int slot  = PMAJ ? (idx & 31) : (idx >> 5);
        if (lane == owner) {
            #pragma unroll
            for (int j = 0; j < NL; j++) if (j == slot) kk[j] = 0ull;
        }
    }
}

__global__ void topk_kernel() {
    const int gw   = (blockIdx.x * blockDim.x + threadIdx.x) >> 5;  // token
    const int lane = threadIdx.x & 31;
    const float* s1 = g_s1 + (size_t)gw * NKEYS;
    const float* s2 = g_s2 + (size_t)gw * NKEYS;

    float s1v = 0.f, s2v = 0.f, selv = 0.f;
    int   s1i = 0,   s2i = 0,   selp = 0;

    {
        ull kk[16];
        #pragma unroll
        for (int j = 0; j < 16; j++) { int idx = j * 32 + lane; kk[j] = mkkey(s1[idx], idx); }
        select32<16, false>(kk, lane, s1v, s1i);
    }
    {
        ull kk[16];
        #pragma unroll
        for (int j = 0; j < 16; j++) { int idx = j * 32 + lane; kk[j] = mkkey(s2[idx], idx); }
        select32<16, false>(kk, lane, s2v, s2i);
    }
    {
        // combined 32x32 grid: lane = rank i in s1, j = rank in s2, p = i*32 + j
        ull kk[32];
        #pragma unroll
        for (int j = 0; j < 32; j++) {
            float v2 = __shfl_sync(0xFFFFFFFFu, s2v, j);
            kk[j] = mkkey(s1v + v2, lane * 32 + j);
        }
        select32<32, true>(kk, lane, selv, selp);
    }

    // softmax(scores / sqrt(1024)); lane 0 holds the max (selection is descending)
    float m = __shfl_sync(0xFFFFFFFFu, selv, 0);
    float e = __expf((selv - m) * 0.03125f);
    float s = e;
    #pragma unroll
    for (int o = 16; o > 0; o >>= 1) s += __shfl_xor_sync(0xFFFFFFFFu, s, o);
    float w = e / s;

    int i1 = __shfl_sync(0xFFFFFFFFu, s1i, selp >> 5);
    int i2 = __shfl_sync(0xFFFFFFFFu, s2i, selp & 31);
    g_tidx[gw * PTOPK + lane] = i1 * NKEYS + i2;
    g_tw  [gw * PTOPK + lane] = w;
}

// ---------------- gather + weighted sum + gate (HBM-bound: ~512 MB of values) ----------
__global__ void gather_kernel(const float* __restrict__ values) {
    const int token = blockIdx.x;
    const int tid   = threadIdx.x;
    __shared__ int   sidx[PTOPK];
    __shared__ float sw  [PTOPK];
    if (tid < PTOPK) {
        sidx[tid] = g_tidx[token * PTOPK + tid];
        sw  [tid] = g_tw  [token * PTOPK + tid];
    }
    __syncthreads();

    float4 acc = make_float4(0.f, 0.f, 0.f, 0.f);
    #pragma unroll 8
    for (int k = 0; k < PTOPK; k++) {
        const float4* row = (const float4*)(values + (size_t)sidx[k] * PDIM);
        float4 v = __ldg(row + tid);
        float wk = sw[k];
        acc.x += wk * v.x; acc.y += wk * v.y; acc.z += wk * v.z; acc.w += wk * v.w;
    }
    float4 g = ((const float4*)(g_gate + (size_t)token * PDIM))[tid];
    acc.x *= g.x; acc.y *= g.y; acc.z *= g.z; acc.w *= g.w;
    ((float4*)(g_mid + (size_t)token * PDIM))[tid] = acc;
}

// ---------------- launch ----------------
extern "C" void kernel_launch(void* const* d_in, const int* in_sizes, int n_in,
                              void* d_out, int out_size) {
    (void)in_sizes; (void)n_in; (void)out_size;
    const float* x      = (const float*)d_in[0];
    const float* ke1    = (const float*)d_in[1];
    const float* ke2    = (const float*)d_in[2];
    const float* values = (const float*)d_in[3];
    const float* Wq     = (const float*)d_in[4];
    const float* bq     = (const float*)d_in[5];
    const float* Wg     = (const float*)d_in[6];
    const float* bg     = (const float*)d_in[7];
    const float* Wo     = (const float*)d_in[8];
    const float* bo     = (const float*)d_in[9];
    float* out = (float*)d_out;

    float *q, *gt, *s1, *s2, *mid;
    cudaGetSymbolAddress((void**)&q,   g_query);
    cudaGetSymbolAddress((void**)&gt,  g_gate);
    cudaGetSymbolAddress((void**)&s1,  g_s1);
    cudaGetSymbolAddress((void**)&s2,  g_s2);
    cudaGetSymbolAddress((void**)&mid, g_mid);

    dim3 blk(256);
    // query = x @ Wq^T + bq
    gemm_tn<<<dim3(PDIM / BN, TOKENS / BM), blk>>>(x, Wq, bq, q, PDIM, PDIM, PDIM, PDIM, 0);
    // gate = silu(x @ Wg^T + bg)
    gemm_tn<<<dim3(PDIM / BN, TOKENS / BM), blk>>>(x, Wg, bg, gt, PDIM, PDIM, PDIM, PDIM, 1);
    // scores1 = q[:, :512] @ ke1^T ; scores2 = q[:, 512:] @ ke2^T
    gemm_tn<<<dim3(NKEYS / BN, TOKENS / BM), blk>>>(q,        ke1, nullptr, s1, PHALF, PDIM, PHALF, NKEYS, 0);
    gemm_tn<<<dim3(NKEYS / BN, TOKENS / BM), blk>>>(q + PHALF, ke2, nullptr, s2, PHALF, PDIM, PHALF, NKEYS, 0);
    // two-stage top-k + softmax weights (warp per token)
    topk_kernel<<<TOKENS / 8, 256>>>();
    // weighted gather of values rows, times gate
    gather_kernel<<<TOKENS, 256>>>(values);
    // out = mid @ Wo^T + bo
    gemm_tn<<<dim3(PDIM / BN, TOKENS / BM), blk>>>(mid, Wo, bo, out, PDIM, PDIM, PDIM, PDIM, 0);
}

// round 5
// speedup vs baseline: 1.0764x; 1.0764x over previous
#include <cuda_runtime.h>
#include <cstdint>

typedef unsigned long long ull;

#define TOKENS 4096
#define PDIM   1024
#define PHALF  512
#define NKEYS  512
#define PTOPK  32

// ---------------- scratch (static device allocations; no cudaMalloc) ----------------
__device__ float g_query[TOKENS * PDIM];
__device__ float g_gate [TOKENS * PDIM];
__device__ float g_s1   [TOKENS * NKEYS];
__device__ float g_s2   [TOKENS * NKEYS];
__device__ float g_mid  [TOKENS * PDIM];
__device__ int   g_tidx [TOKENS * PTOPK];
__device__ float g_tw   [TOKENS * PTOPK];

// ---------------- f32x2 packed-FMA helpers (Blackwell FFMA2 path) ----------------
__device__ __forceinline__ void fma2(ull &acc, ull a, ull b) {
    asm("fma.rn.f32x2 %0, %1, %2, %3;" : "=l"(acc) : "l"(a), "l"(b), "l"(acc));
}
__device__ __forceinline__ ull dup2(float a) {
    ull r; asm("mov.b64 %0, {%1, %1};" : "=l"(r) : "f"(a)); return r;
}
__device__ __forceinline__ float2 upk2(ull v) {
    float2 r; asm("mov.b64 {%0, %1}, %2;" : "=f"(r.x), "=f"(r.y) : "l"(v)); return r;
}

// ---------------- fused TN SGEMM, double-buffered smem ----------------
// C[M,N] = A[M,K] * B[N,K]^T (+bias, optional silu).
// Grid.x is split: blocks [0, nx0) use {B0,bias0,C0,act0}; blocks [nx0, ...)
// use {B1,bias1,C1,act1} with A column-offset aoff1. Lets two GEMMs sharing A
// (Wq+Wg, s1+s2) run as ONE launch with a bigger grid (wave efficiency +
// 2 CTAs/SM occupancy).
#define BM 128
#define BN 128
#define BK 16

__global__ __launch_bounds__(256, 2)
void gemm_tn(const float* __restrict__ A,
             const float* __restrict__ B0, const float* __restrict__ B1,
             const float* __restrict__ bias0, const float* __restrict__ bias1,
             float* __restrict__ C0, float* __restrict__ C1,
             int K, int lda, int ldb, int ldc,
             int nx0, int aoff1, int act0, int act1)
{
    __shared__ __align__(16) float As[2][BK][BM + 4];
    __shared__ __align__(16) float Bs[2][BK][BN + 4];

    const bool sec = (int)blockIdx.x >= nx0;
    const float* B    = sec ? B1    : B0;
    const float* bias = sec ? bias1 : bias0;
    float*       C    = sec ? C1    : C0;
    const int    act  = sec ? act1  : act0;
    const int    bn   = (sec ? (int)blockIdx.x - nx0 : (int)blockIdx.x) * BN;
    const float* Ab   = A + (sec ? aoff1 : 0);

    const int tid = threadIdx.x;
    const int bm  = blockIdx.y * BM;
    const int lr  = tid >> 2;          // 0..63
    const int lc  = (tid & 3) * 4;     // 0,4,8,12 (k-direction)
    const int tx  = tid & 15;
    const int ty  = tid >> 4;

    const float* Ap0 = Ab + (size_t)(bm + lr) * lda + lc;
    const float* Ap1 = Ap0 + (size_t)64 * lda;
    const float* Bp0 = B + (size_t)(bn + lr) * ldb + lc;
    const float* Bp1 = Bp0 + (size_t)64 * ldb;

    float4 av0 = *(const float4*)Ap0;
    float4 av1 = *(const float4*)Ap1;
    float4 bv0 = *(const float4*)Bp0;
    float4 bv1 = *(const float4*)Bp1;

    ull acc[8][4];
    #pragma unroll
    for (int r = 0; r < 8; r++)
        #pragma unroll
        for (int c = 0; c < 4; c++) acc[r][c] = 0ull;

    // stash first tile into stage 0
    As[0][lc + 0][lr]      = av0.x; As[0][lc + 1][lr]      = av0.y;
    As[0][lc + 2][lr]      = av0.z; As[0][lc + 3][lr]      = av0.w;
    As[0][lc + 0][lr + 64] = av1.x; As[0][lc + 1][lr + 64] = av1.y;
    As[0][lc + 2][lr + 64] = av1.z; As[0][lc + 3][lr + 64] = av1.w;
    Bs[0][lc + 0][lr]      = bv0.x; Bs[0][lc + 1][lr]      = bv0.y;
    Bs[0][lc + 2][lr]      = bv0.z; Bs[0][lc + 3][lr]      = bv0.w;
    Bs[0][lc + 0][lr + 64] = bv1.x; Bs[0][lc + 1][lr + 64] = bv1.y;
    Bs[0][lc + 2][lr + 64] = bv1.z; Bs[0][lc + 3][lr + 64] = bv1.w;
    __syncthreads();

    int st = 0;
    for (int k0 = 0; k0 < K; k0 += BK) {
        const bool more = (k0 + BK) < K;
        if (more) {  // prefetch next tile while computing current
            av0 = *(const float4*)(Ap0 + k0 + BK);
            av1 = *(const float4*)(Ap1 + k0 + BK);
            bv0 = *(const float4*)(Bp0 + k0 + BK);
            bv1 = *(const float4*)(Bp1 + k0 + BK);
        }

        #pragma unroll
        for (int k = 0; k < BK; k++) {
            float4 a0 = *(const float4*)&As[st][k][ty * 8];
            float4 a1 = *(const float4*)&As[st][k][ty * 8 + 4];
            ulonglong2 bq0 = *(const ulonglong2*)&Bs[st][k][tx * 8];
            ulonglong2 bq1 = *(const ulonglong2*)&Bs[st][k][tx * 8 + 4];
            ull bb[4] = { bq0.x, bq0.y, bq1.x, bq1.y };
            ull aa[8] = { dup2(a0.x), dup2(a0.y), dup2(a0.z), dup2(a0.w),
                          dup2(a1.x), dup2(a1.y), dup2(a1.z), dup2(a1.w) };
            #pragma unroll
            for (int r = 0; r < 8; r++)
                #pragma unroll
                for (int c = 0; c < 4; c++) fma2(acc[r][c], aa[r], bb[c]);
        }

        if (more) {
            const int ns = st ^ 1;
            As[ns][lc + 0][lr]      = av0.x; As[ns][lc + 1][lr]      = av0.y;
            As[ns][lc + 2][lr]      = av0.z; As[ns][lc + 3][lr]      = av0.w;
            As[ns][lc + 0][lr + 64] = av1.x; As[ns][lc + 1][lr + 64] = av1.y;
            As[ns][lc + 2][lr + 64] = av1.z; As[ns][lc + 3][lr + 64] = av1.w;
            Bs[ns][lc + 0][lr]      = bv0.x; Bs[ns][lc + 1][lr]      = bv0.y;
            Bs[ns][lc + 2][lr]      = bv0.z; Bs[ns][lc + 3][lr]      = bv0.w;
            Bs[ns][lc + 0][lr + 64] = bv1.x; Bs[ns][lc + 1][lr + 64] = bv1.y;
            Bs[ns][lc + 2][lr + 64] = bv1.z; Bs[ns][lc + 3][lr + 64] = bv1.w;
        }
        __syncthreads();
        st ^= 1;
    }

    #pragma unroll
    for (int c = 0; c < 4; c++) {
        int col = bn + tx * 8 + 2 * c;
        float b0 = 0.f, b1 = 0.f;
        if (bias) { b0 = bias[col]; b1 = bias[col + 1]; }
        #pragma unroll
        for (int r = 0; r < 8; r++) {
            float2 v = upk2(acc[r][c]);
            v.x += b0; v.y += b1;
            if (act) {  // silu
                v.x = v.x * (1.f / (1.f + __expf(-v.x)));
                v.y = v.y * (1.f / (1.f + __expf(-v.y)));
            }
            *(float2*)&C[(size_t)(bm + ty * 8 + r) * ldc + col] = v;
        }
    }
}

// ---------------- top-k (warp per token, registers only) ----------------
// Keys pack (orderable-float << 32) | (0xFFFFFFFF - idx): max-key == jax top_k
// semantics (value descending, ties -> smaller index).
__device__ __forceinline__ unsigned ford(float v) {
    unsigned u = __float_as_uint(v);
    return (u & 0x80000000u) ? ~u : (u | 0x80000000u);
}
__device__ __forceinline__ float funord(unsigned k) {
    unsigned u = (k & 0x80000000u) ? (k ^ 0x80000000u) : ~k;
    return __uint_as_float(u);
}
__device__ __forceinline__ ull mkkey(float v, int idx) {
    return ((ull)ford(v) << 32) | (unsigned)(0xFFFFFFFFu - (unsigned)idx);
}

// stage 1/2: top-32 of 512; idx = j*32 + lane (owner = idx&31, slot = idx>>5)
__device__ __forceinline__ void select32_512(ull* kk, int lane, float &ov, int &oi) {
    for (int it = 0; it < PTOPK; ++it) {
        ull best = kk[0];
        #pragma unroll
        for (int j = 1; j < 16; j++) if (kk[j] > best) best = kk[j];
        #pragma unroll
        for (int o = 16; o > 0; o >>= 1) {
            ull t = __shfl_xor_sync(0xFFFFFFFFu, best, o);
            if (t > best) best = t;
        }
        int idx = (int)(0xFFFFFFFFu - (unsigned)best);
        if (lane == it) { ov = funord((unsigned)(best >> 32)); oi = idx; }
        int owner = idx & 31;
        int slot  = idx >> 5;
        if (lane == owner) {
            #pragma unroll
            for (int j = 0; j < 16; j++) if (j == slot) kk[j] = 0ull;
        }
    }
}

__global__ void topk_kernel() {
    const int gw   = (blockIdx.x * blockDim.x + threadIdx.x) >> 5;  // token
    const int lane = threadIdx.x & 31;
    const float* s1 = g_s1 + (size_t)gw * NKEYS;
    const float* s2 = g_s2 + (size_t)gw * NKEYS;

    float s1v = 0.f, s2v = 0.f, selv = 0.f;
    int   s1i = 0,   s2i = 0,   selp = 0;

    {
        ull kk[16];
        #pragma unroll
        for (int j = 0; j < 16; j++) { int idx = j * 32 + lane; kk[j] = mkkey(s1[idx], idx); }
        select32_512(kk, lane, s1v, s1i);
    }
    {
        ull kk[16];
        #pragma unroll
        for (int j = 0; j < 16; j++) { int idx = j * 32 + lane; kk[j] = mkkey(s2[idx], idx); }
        select32_512(kk, lane, s2v, s2i);
    }

    // Stage 3: top-32 of the 32x32 sum grid. s1v (lane = rank i) and s2v
    // (lane = rank j) are rank-sorted descending across lanes with exact
    // jax tie-breaking, so each lane's candidate list s1v + s2v[p]
    // (position = lane*32 + p) is sorted by composite key. Pointer-walk:
    // each lane exposes one candidate; warp float-max + ballot picks the
    // winner; lowest set lane = lowest position = jax tie-break.
    {
        int p = 0;
        float v = s1v + __shfl_sync(0xFFFFFFFFu, s2v, 0);
        for (int it = 0; it < PTOPK; ++it) {
            float bv = v;
            #pragma unroll
            for (int o = 16; o > 0; o >>= 1)
                bv = fmaxf(bv, __shfl_xor_sync(0xFFFFFFFFu, bv, o));
            unsigned m = __ballot_sync(0xFFFFFFFFu, v == bv);
            int wl = __ffs(m) - 1;
            int wp = __shfl_sync(0xFFFFFFFFu, p, wl);
            if (lane == it) { selv = bv; selp = wl * 32 + wp; }
            bool won = (lane == wl);
            p += won;
            float ns2 = __shfl_sync(0xFFFFFFFFu, s2v, p < 32 ? p : 31);
            if (won) v = (p < 32) ? (s1v + ns2) : -3.4e38f;
        }
    }

    // softmax(scores / sqrt(1024)); lane 0 holds the max (selection is descending)
    float mx = __shfl_sync(0xFFFFFFFFu, selv, 0);
    float e = __expf((selv - mx) * 0.03125f);
    float s = e;
    #pragma unroll
    for (int o = 16; o > 0; o >>= 1) s += __shfl_xor_sync(0xFFFFFFFFu, s, o);
    float w = e / s;

    int i1 = __shfl_sync(0xFFFFFFFFu, s1i, selp >> 5);
    int i2 = __shfl_sync(0xFFFFFFFFu, s2i, selp & 31);
    g_tidx[gw * PTOPK + lane] = i1 * NKEYS + i2;
    g_tw  [gw * PTOPK + lane] = w;
}

// ---------------- gather + weighted sum + gate (HBM-bound: ~512 MB of values) ----------
__global__ void gather_kernel(const float* __restrict__ values) {
    const int token = blockIdx.x;
    const int tid   = threadIdx.x;
    __shared__ int   sidx[PTOPK];
    __shared__ float sw  [PTOPK];
    if (tid < PTOPK) {
        sidx[tid] = g_tidx[token * PTOPK + tid];
        sw  [tid] = g_tw  [token * PTOPK + tid];
    }
    __syncthreads();

    float4 acc = make_float4(0.f, 0.f, 0.f, 0.f);
    #pragma unroll 8
    for (int k = 0; k < PTOPK; k++) {
        const float4* row = (const float4*)(values + (size_t)sidx[k] * PDIM);
        float4 v = __ldg(row + tid);
        float wk = sw[k];
        acc.x += wk * v.x; acc.y += wk * v.y; acc.z += wk * v.z; acc.w += wk * v.w;
    }
    float4 g = ((const float4*)(g_gate + (size_t)token * PDIM))[tid];
    acc.x *= g.x; acc.y *= g.y; acc.z *= g.z; acc.w *= g.w;
    ((float4*)(g_mid + (size_t)token * PDIM))[tid] = acc;
}

// ---------------- launch ----------------
extern "C" void kernel_launch(void* const* d_in, const int* in_sizes, int n_in,
                              void* d_out, int out_size) {
    (void)in_sizes; (void)n_in; (void)out_size;
    const float* x      = (const float*)d_in[0];
    const float* ke1    = (const float*)d_in[1];
    const float* ke2    = (const float*)d_in[2];
    const float* values = (const float*)d_in[3];
    const float* Wq     = (const float*)d_in[4];
    const float* bq     = (const float*)d_in[5];
    const float* Wg     = (const float*)d_in[6];
    const float* bg     = (const float*)d_in[7];
    const float* Wo     = (const float*)d_in[8];
    const float* bo     = (const float*)d_in[9];
    float* out = (float*)d_out;

    float *q, *gt, *s1, *s2, *mid;
    cudaGetSymbolAddress((void**)&q,   g_query);
    cudaGetSymbolAddress((void**)&gt,  g_gate);
    cudaGetSymbolAddress((void**)&s1,  g_s1);
    cudaGetSymbolAddress((void**)&s2,  g_s2);
    cudaGetSymbolAddress((void**)&mid, g_mid);

    dim3 blk(256);
    // fused: query = x@Wq^T + bq  ||  gate = silu(x@Wg^T + bg)   (grid 512)
    gemm_tn<<<dim3(16, TOKENS / BM), blk>>>(x, Wq, Wg, bq, bg, q, gt,
                                            PDIM, PDIM, PDIM, PDIM,
                                            /*nx0=*/8, /*aoff1=*/0, 0, 1);
    // fused: s1 = q[:, :512]@ke1^T  ||  s2 = q[:, 512:]@ke2^T    (grid 256)
    gemm_tn<<<dim3(8, TOKENS / BM), blk>>>(q, ke1, ke2, nullptr, nullptr, s1, s2,
                                           PHALF, PDIM, PHALF, NKEYS,
                                           /*nx0=*/4, /*aoff1=*/PHALF, 0, 0);
    // two-stage top-k + softmax weights (warp per token)
    topk_kernel<<<TOKENS / 8, 256>>>();
    // weighted gather of values rows, times gate
    gather_kernel<<<TOKENS, 256>>>(values);
    // out = mid@Wo^T + bo                                        (grid 256)
    gemm_tn<<<dim3(8, TOKENS / BM), blk>>>(mid, Wo, Wo, bo, bo, out, out,
                                           PDIM, PDIM, PDIM, PDIM,
                                           /*nx0=*/8, /*aoff1=*/0, 0, 0);
}